// round 17
// baseline (speedup 1.0000x reference)
#include <cuda_runtime.h>
#include <cuda_fp16.h>
#include <cstdint>
#include <math.h>

// ---------------- problem constants ----------------
#define T_TOK   4096
#define H_DIM   1024
#define I_DIM   2048
#define E_NUM   8
#define NSLOT   (T_TOK * 2)
#define ROW_TILES 71          // sum ceil(cnt_e/128) <= 64 + 7

#define BKH   32              // K halfs per stage
#define RSTRA 80              // A row stride bytes (K-major rows)
#define RSTRB 272             // B row stride bytes (N-major rows, 256B data + 16 pad)
#define TILE0 1152            // tile region start in dynamic smem
#define NSTG  3

#define G1_A_B     (128 * RSTRA)             // 10240
#define G1_BB      (32 * RSTRB)              // 8704 per matrix
#define G1_STAGE_B (G1_A_B + 2 * G1_BB)      // 27648
#define G1_SMEM    (TILE0 + NSTG * G1_STAGE_B)
#define G2_STAGE_B (G1_A_B + G1_BB)          // 18944
#define G2_SMEM    (TILE0 + NSTG * G2_STAGE_B)

// ---------------- device scratch ----------------
__device__ int   g_cnt[E_NUM];
__device__ int   g_off[E_NUM + 1];
__device__ int   g_tok_exp[NSLOT];
__device__ float g_tok_wt[NSLOT];
__device__ int   g_tok_rank[NSLOT];
__device__ int   g_perm[NSLOT];
__device__ int   g_slot_of[NSLOT];

__device__ __half g_xh [(size_t)T_TOK * H_DIM];                // x fp16 [t][k]
__device__ __half g_wg [(size_t)E_NUM * H_DIM * I_DIM];        // gate fp16 [e][k in H][n in I]
__device__ __half g_wu [(size_t)E_NUM * H_DIM * I_DIM];        // up   fp16 same layout
__device__ __half g_w2 [(size_t)E_NUM * I_DIM * H_DIM];        // down fp16 [e][k in I][n in H]
__device__ __half g_hid[(size_t)(NSLOT + 128) * I_DIM];        // hidden fp16 [slot][k]
__device__ float  g_y  [(size_t)(NSLOT + 128) * H_DIM];        // per-slot down output

// ---------------- PTX helpers ----------------
__device__ __forceinline__ uint32_t smem_u32(const void* p) {
    uint32_t a;
    asm("{ .reg .u64 t; cvta.to.shared.u64 t, %1; cvt.u32.u64 %0, t; }" : "=r"(a) : "l"(p));
    return a;
}
#define CPA16(dst, src) \
    asm volatile("cp.async.cg.shared.global [%0], [%1], 16;" :: "r"(dst), "l"(src))
#define CPCOMMIT() asm volatile("cp.async.commit_group;" ::: "memory")
#define CPWAIT1()  asm volatile("cp.async.wait_group 1;" ::: "memory")

#define LDM4(r, addr) \
    asm volatile("ldmatrix.sync.aligned.m8n8.x4.shared.b16 {%0,%1,%2,%3}, [%4];" \
        : "=r"((r)[0]), "=r"((r)[1]), "=r"((r)[2]), "=r"((r)[3]) : "r"(addr))
#define LDM4T(r, addr) \
    asm volatile("ldmatrix.sync.aligned.m8n8.x4.trans.shared.b16 {%0,%1,%2,%3}, [%4];" \
        : "=r"((r)[0]), "=r"((r)[1]), "=r"((r)[2]), "=r"((r)[3]) : "r"(addr))

#define MMA16816(c, a, b0v, b1v) \
    asm volatile("mma.sync.aligned.m16n8k16.row.col.f32.f16.f16.f32 " \
        "{%0,%1,%2,%3}, {%4,%5,%6,%7}, {%8,%9}, {%0,%1,%2,%3};" \
        : "+f"((c)[0]), "+f"((c)[1]), "+f"((c)[2]), "+f"((c)[3]) \
        : "r"((a)[0]), "r"((a)[1]), "r"((a)[2]), "r"((a)[3]), "r"(b0v), "r"(b1v))

// ---------------- launch 0: cast all weights fp32 -> fp16 (same layout) ----------------
__global__ void conv_w_all(const float* __restrict__ gw,
                           const float* __restrict__ uw,
                           const float* __restrict__ ow) {
    if (blockIdx.x == 0 && blockIdx.y == 0 && threadIdx.x < E_NUM)
        g_cnt[threadIdx.x] = 0;
    const float* src = (blockIdx.y == 0) ? gw : (blockIdx.y == 1) ? uw : ow;
    __half* dst = (blockIdx.y == 0) ? g_wg : (blockIdx.y == 1) ? g_wu : g_w2;
    size_t i = ((size_t)blockIdx.x * blockDim.x + threadIdx.x) * 4;
    float4 v = *(const float4*)(src + i);
    __half2 a = __floats2half2_rn(v.x, v.y);
    __half2 b = __floats2half2_rn(v.z, v.w);
    *(uint2*)(dst + i) = make_uint2(*(uint32_t*)&a, *(uint32_t*)&b);
}

// ---------------- launch 1: router (+ x fp16 conversion fused) ----------------
__global__ void router_kernel(const float* __restrict__ x,
                              const float* __restrict__ rw,
                              float* __restrict__ logits_out,
                              int write_logits) {
    int t = blockIdx.x;
    int warp = threadIdx.x >> 5, lane = threadIdx.x & 31;
    const float* xr = x + (size_t)t * H_DIM;
    {
        int c = threadIdx.x * 4;
        float4 v = *(const float4*)(xr + c);
        __half2 a = __floats2half2_rn(v.x, v.y);
        __half2 b = __floats2half2_rn(v.z, v.w);
        *(uint2*)(g_xh + (size_t)t * H_DIM + c) = make_uint2(*(uint32_t*)&a, *(uint32_t*)&b);
    }
    float s = 0.f;
    for (int h = lane; h < H_DIM; h += 32)
        s += xr[h] * rw[h * E_NUM + warp];
#pragma unroll
    for (int o = 16; o; o >>= 1) s += __shfl_xor_sync(0xffffffffu, s, o);
    __shared__ float lg[E_NUM];
    if (lane == 0) lg[warp] = s;
    __syncthreads();
    if (threadIdx.x == 0) {
        float l[E_NUM], mx = -1e30f;
#pragma unroll
        for (int e = 0; e < E_NUM; e++) { l[e] = lg[e]; mx = fmaxf(mx, l[e]); }
        float p[E_NUM], sum = 0.f;
#pragma unroll
        for (int e = 0; e < E_NUM; e++) { p[e] = expf(l[e] - mx); sum += p[e]; }
#pragma unroll
        for (int e = 0; e < E_NUM; e++) p[e] /= sum;
        int i1 = 0;
#pragma unroll
        for (int e = 1; e < E_NUM; e++) if (p[e] > p[i1]) i1 = e;
        int i2 = (i1 == 0) ? 1 : 0;
#pragma unroll
        for (int e = 0; e < E_NUM; e++) if (e != i1 && p[e] > p[i2]) i2 = e;
        float denom = p[i1] + p[i2];
        int r1 = atomicAdd(&g_cnt[i1], 1);
        int r2 = atomicAdd(&g_cnt[i2], 1);
        g_tok_exp[2 * t]     = i1; g_tok_wt[2 * t]     = p[i1] / denom; g_tok_rank[2 * t]     = r1;
        g_tok_exp[2 * t + 1] = i2; g_tok_wt[2 * t + 1] = p[i2] / denom; g_tok_rank[2 * t + 1] = r2;
        if (write_logits) {
#pragma unroll
            for (int e = 0; e < E_NUM; e++)
                logits_out[(size_t)t * E_NUM + e] = l[e];
        }
    }
}

// ---------------- launch 2: scan offsets + build permutation (one block) ----------------
__global__ void scanperm_kernel() {
    __shared__ int off[E_NUM + 1];
    if (threadIdx.x == 0) {
        int a = 0;
        for (int e = 0; e < E_NUM; e++) { off[e] = a; g_off[e] = a; a += g_cnt[e]; }
        off[E_NUM] = a; g_off[E_NUM] = a;
    }
    __syncthreads();
    for (int idx = threadIdx.x; idx < NSLOT; idx += blockDim.x) {
        int e = g_tok_exp[idx];
        int slot = off[e] + g_tok_rank[idx];
        g_perm[slot] = idx >> 1;
        g_slot_of[idx] = slot;
    }
}

// ---------------- tile resolver ----------------
__device__ __forceinline__ void resolve_tile(int* hdr) {
    if (threadIdx.x == 0) {
        int b = blockIdx.x, acc = 0, fe = -1, fr = 0, fn = 0;
        for (int e = 0; e < E_NUM; e++) {
            int c = g_off[e + 1] - g_off[e];
            int nt = (c + 127) >> 7;
            if (fe < 0 && b < acc + nt) { fe = e; fr = g_off[e] + (b - acc) * 128; fn = g_off[e] + c; }
            acc += nt;
        }
        hdr[0] = fe; hdr[1] = fr; hdr[2] = fn;
    }
}

// ---------------- launch 3: GEMM1 hidden = silu(x@gate)*(x@up) ----------------
// 512 threads, 16 warps (4m x 4n), warp tile 32x32, CTA tile 128x128
__global__ void __launch_bounds__(512)
gemm1_mma() {
    extern __shared__ char dsm[];
    int tid = threadIdx.x, warp = tid >> 5, lane = tid & 31;
    int* hdr = (int*)dsm;
    int* s_tok = (int*)(dsm + 64);
    resolve_tile(hdr);
    __syncthreads();
    int e = hdr[0];
    if (e < 0) return;
    int row0 = hdr[1], rend = hdr[2];
    int n0 = blockIdx.y * 128;
    if (tid < 128) {
        int r = row0 + tid;
        s_tok[tid] = g_perm[(r < rend) ? r : row0];
    }
    __syncthreads();
    uint32_t sb = smem_u32(dsm);

    // A loads: 128 rows x 64B; thread -> row = tid>>2, 16B chunk = tid&3
    int lrow = tid >> 2, seg = tid & 3;
    const char* aP = (const char*)(g_xh + (size_t)s_tok[lrow] * H_DIM) + seg * 16;
    uint32_t dA0 = sb + TILE0 + lrow * RSTRA + seg * 16;
    // B loads: 32 rows x 256B; thread -> row = tid>>4, 16B chunk = tid&15
    int brow = tid >> 4, bc = tid & 15;
    const char* gP = (const char*)(g_wg + ((size_t)e * H_DIM + brow) * I_DIM + n0 + bc * 8);
    const char* uP = (const char*)(g_wu + ((size_t)e * H_DIM + brow) * I_DIM + n0 + bc * 8);
    uint32_t dB0 = sb + TILE0 + G1_A_B + brow * RSTRB + bc * 16;

#define G1LOAD(bufo, k0) { \
        CPA16(dA0 + (bufo), aP + (k0) * 2); \
        int kb = (k0) * (I_DIM * 2); \
        CPA16(dB0 + (bufo),         gP + kb); \
        CPA16(dB0 + (bufo) + G1_BB, uP + kb); }

    float cg[2][4][4], cu[2][4][4];
#pragma unroll
    for (int i = 0; i < 2; i++)
#pragma unroll
        for (int j = 0; j < 4; j++)
#pragma unroll
            for (int q = 0; q < 4; q++) { cg[i][j][q] = 0.f; cu[i][j][q] = 0.f; }

    G1LOAD(0, 0); CPCOMMIT();
    G1LOAD(G1_STAGE_B, BKH); CPCOMMIT();

    int wm = warp & 3, wn = warp >> 2;                  // 4m x 4n warps
    uint32_t aOff = TILE0 + (wm * 32 + (lane & 15)) * RSTRA + ((lane >> 4) & 1) * 16;
    int grp = lane >> 3, bj = lane & 7;
    uint32_t bOff = TILE0 + G1_A_B + ((grp & 1) * 8 + bj) * RSTRB
                  + (wn * 32 + (grp >> 1) * 8) * 2;

    const int NS = H_DIM / BKH;   // 32 stages
    int cOff = 0, wOff = 2 * G1_STAGE_B;
    for (int s = 0; s < NS; s++) {
        CPWAIT1();
        __syncthreads();
        if (s + 2 < NS) { G1LOAD(wOff, (s + 2) * BKH); }
        CPCOMMIT();
        uint32_t bA = sb + aOff + cOff;
        uint32_t bB = sb + bOff + cOff;
#pragma unroll
        for (int k16 = 0; k16 < 2; k16++) {
            uint32_t a0[4], a1[4];
            LDM4(a0, bA + k16 * 32);
            LDM4(a1, bA + 16 * RSTRA + k16 * 32);
#pragma unroll
            for (int q = 0; q < 2; q++) {
                uint32_t bg[4], bu[4];
                LDM4T(bg, bB + k16 * (16 * RSTRB) + q * 32);
                LDM4T(bu, bB + G1_BB + k16 * (16 * RSTRB) + q * 32);
                MMA16816(cg[0][2 * q],     a0, bg[0], bg[1]);
                MMA16816(cg[0][2 * q + 1], a0, bg[2], bg[3]);
                MMA16816(cg[1][2 * q],     a1, bg[0], bg[1]);
                MMA16816(cg[1][2 * q + 1], a1, bg[2], bg[3]);
                MMA16816(cu[0][2 * q],     a0, bu[0], bu[1]);
                MMA16816(cu[0][2 * q + 1], a0, bu[2], bu[3]);
                MMA16816(cu[1][2 * q],     a1, bu[0], bu[1]);
                MMA16816(cu[1][2 * q + 1], a1, bu[2], bu[3]);
            }
        }
        cOff += G1_STAGE_B; if (cOff == NSTG * G1_STAGE_B) cOff = 0;
        wOff += G1_STAGE_B; if (wOff == NSTG * G1_STAGE_B) wOff = 0;
    }
#undef G1LOAD

    // epilogue: silu(g)*u -> fp16 hidden
    int rA = wm * 32 + (lane >> 2);
    int cBase = n0 + wn * 32 + 2 * (lane & 3);
#pragma unroll
    for (int mt = 0; mt < 2; mt++) {
#pragma unroll
        for (int nt = 0; nt < 4; nt++) {
            int col = cBase + nt * 8;
            int r0r = rA + mt * 16;
            float* g0 = cg[mt][nt];
            float* u0 = cu[mt][nt];
            if (row0 + r0r < rend) {
                float h0 = u0[0] * (g0[0] / (1.f + __expf(-g0[0])));
                float h1 = u0[1] * (g0[1] / (1.f + __expf(-g0[1])));
                __half2 hv = __floats2half2_rn(h0, h1);
                *(__half2*)(g_hid + (size_t)(row0 + r0r) * I_DIM + col) = hv;
            }
            if (row0 + r0r + 8 < rend) {
                float h2 = u0[2] * (g0[2] / (1.f + __expf(-g0[2])));
                float h3 = u0[3] * (g0[3] / (1.f + __expf(-g0[3])));
                __half2 hv = __floats2half2_rn(h2, h3);
                *(__half2*)(g_hid + (size_t)(row0 + r0r + 8) * I_DIM + col) = hv;
            }
        }
    }
}

// ---------------- launch 4: GEMM2 y[slot] = hidden @ down ----------------
__global__ void __launch_bounds__(512)
gemm2_mma() {
    extern __shared__ char dsm[];
    int tid = threadIdx.x, warp = tid >> 5, lane = tid & 31;
    int* hdr = (int*)dsm;
    resolve_tile(hdr);
    __syncthreads();
    int e = hdr[0];
    if (e < 0) return;
    int row0 = hdr[1], rend = hdr[2];
    int n0 = blockIdx.y * 128;
    uint32_t sb = smem_u32(dsm);

    int lrow = tid >> 2, seg = tid & 3;
    const char* aP = (const char*)(g_hid + (size_t)(row0 + lrow) * I_DIM) + seg * 16;
    uint32_t dA0 = sb + TILE0 + lrow * RSTRA + seg * 16;
    int brow = tid >> 4, bc = tid & 15;
    const char* bP = (const char*)(g_w2 + ((size_t)e * I_DIM + brow) * H_DIM + n0 + bc * 8);
    uint32_t dB0 = sb + TILE0 + G1_A_B + brow * RSTRB + bc * 16;

#define G2LOAD(bufo, k0) { \
        CPA16(dA0 + (bufo), aP + (k0) * 2); \
        CPA16(dB0 + (bufo), bP + (k0) * (H_DIM * 2)); }

    float cc[2][4][4];
#pragma unroll
    for (int i = 0; i < 2; i++)
#pragma unroll
        for (int j = 0; j < 4; j++)
#pragma unroll
            for (int q = 0; q < 4; q++) cc[i][j][q] = 0.f;

    G2LOAD(0, 0); CPCOMMIT();
    G2LOAD(G2_STAGE_B, BKH); CPCOMMIT();

    int wm = warp & 3, wn = warp >> 2;
    uint32_t aOff = TILE0 + (wm * 32 + (lane & 15)) * RSTRA + ((lane >> 4) & 1) * 16;
    int grp = lane >> 3, bj = lane & 7;
    uint32_t bOff = TILE0 + G1_A_B + ((grp & 1) * 8 + bj) * RSTRB
                  + (wn * 32 + (grp >> 1) * 8) * 2;

    const int NS = I_DIM / BKH;   // 64 stages
    int cOff = 0, wOff = 2 * G2_STAGE_B;
    for (int s = 0; s < NS; s++) {
        CPWAIT1();
        __syncthreads();
        if (s + 2 < NS) { G2LOAD(wOff, (s + 2) * BKH); }
        CPCOMMIT();
        uint32_t bA = sb + aOff + cOff;
        uint32_t bB = sb + bOff + cOff;
#pragma unroll
        for (int k16 = 0; k16 < 2; k16++) {
            uint32_t a0[4], a1[4];
            LDM4(a0, bA + k16 * 32);
            LDM4(a1, bA + 16 * RSTRA + k16 * 32);
#pragma unroll
            for (int q = 0; q < 2; q++) {
                uint32_t bb[4];
                LDM4T(bb, bB + k16 * (16 * RSTRB) + q * 32);
                MMA16816(cc[0][2 * q],     a0, bb[0], bb[1]);
                MMA16816(cc[0][2 * q + 1], a0, bb[2], bb[3]);
                MMA16816(cc[1][2 * q],     a1, bb[0], bb[1]);
                MMA16816(cc[1][2 * q + 1], a1, bb[2], bb[3]);
            }
        }
        cOff += G2_STAGE_B; if (cOff == NSTG * G2_STAGE_B) cOff = 0;
        wOff += G2_STAGE_B; if (wOff == NSTG * G2_STAGE_B) wOff = 0;
    }
#undef G2LOAD

    int rA = wm * 32 + (lane >> 2);
    int cBase = n0 + wn * 32 + 2 * (lane & 3);
#pragma unroll
    for (int mt = 0; mt < 2; mt++) {
#pragma unroll
        for (int nt = 0; nt < 4; nt++) {
            int col = cBase + nt * 8;
            int r0r = rA + mt * 16;
            float* c0 = cc[mt][nt];
            if (row0 + r0r < rend)
                *(float2*)(g_y + (size_t)(row0 + r0r) * H_DIM + col) =
                    make_float2(c0[0], c0[1]);
            if (row0 + r0r + 8 < rend)
                *(float2*)(g_y + (size_t)(row0 + r0r + 8) * H_DIM + col) =
                    make_float2(c0[2], c0[3]);
        }
    }
}

// ---------------- launch 5: combine out[t] = w0*y[slot0] + w1*y[slot1] ----------------
__global__ void combine_kernel(float* __restrict__ out) {
    int t = blockIdx.x;
    int c = threadIdx.x * 4;
    int s0 = g_slot_of[2 * t], s1 = g_slot_of[2 * t + 1];
    float w0 = g_tok_wt[2 * t], w1 = g_tok_wt[2 * t + 1];
    float4 a = *(const float4*)(g_y + (size_t)s0 * H_DIM + c);
    float4 b = *(const float4*)(g_y + (size_t)s1 * H_DIM + c);
    float4 o;
    o.x = a.x * w0 + b.x * w1;
    o.y = a.y * w0 + b.y * w1;
    o.z = a.z * w0 + b.z * w1;
    o.w = a.w * w0 + b.w * w1;
    *(float4*)(out + (size_t)t * H_DIM + c) = o;
}

// ---------------- launcher ----------------
extern "C" void kernel_launch(void* const* d_in, const int* in_sizes, int n_in,
                              void* d_out, int out_size) {
    const float* x  = (const float*)d_in[0];   // [B,S,H]
    const float* rw = (const float*)d_in[1];   // [H,E]
    const float* gw = (const float*)d_in[2];   // [E,H,I]
    const float* uw = (const float*)d_in[3];   // [E,H,I]
    const float* ow = (const float*)d_in[4];   // [E,I,H]
    float* out = (float*)d_out;

    (void)cudaFuncSetAttribute(gemm1_mma, cudaFuncAttributeMaxDynamicSharedMemorySize, G1_SMEM);
    (void)cudaFuncSetAttribute(gemm2_mma, cudaFuncAttributeMaxDynamicSharedMemorySize, G2_SMEM);

    int write_logits = (out_size >= T_TOK * H_DIM + T_TOK * E_NUM) ? 1 : 0;
    float* logits = out + (size_t)T_TOK * H_DIM;

    conv_w_all<<<dim3(16384, 3), 256>>>(gw, uw, ow);             // launch 0 (+cnt zero)
    router_kernel<<<T_TOK, 256>>>(x, rw, logits, write_logits);  // launch 1 (+x cast)
    scanperm_kernel<<<1, 256>>>();                               // launch 2
    gemm1_mma<<<dim3(ROW_TILES, I_DIM / 128), 512, G1_SMEM>>>(); // launch 3  <- ncu target
    gemm2_mma<<<dim3(ROW_TILES, H_DIM / 128), 512, G2_SMEM>>>(); // launch 4
    combine_kernel<<<T_TOK, 256>>>(out);                         // launch 5
}